// round 17
// baseline (speedup 1.0000x reference)
#include <cuda_runtime.h>
#include <cstdint>

// Embedding gather: out[t, :] = weights[ids[t], :]
// ids: 16384 int32, weights: [50257,1024] fp32, out: [16384,1024] fp32
//
// R16 (WIN, 16.9us wall): MLP_p1=8 via block=128, 2 cols/thread x 4 tokens,
// __launch_bounds__(128,8), regs=48, occ 50.5%. Timed regime is warm-L2
// (weight rows resident across graph replays), so deep per-thread MLP covers
// L2-hit latency; that's what moved the wall time.
// This round: identical kernel body, __launch_bounds__(128, 10). regs=48
// allows 10 CTAs/SM (64K / (48*128) = 10.6): +25% resident warps at the same
// MLP_p1=8 -> more outstanding loads per SM. Key check: regs must stay >=48.

static constexpr int ROW_F4      = 256;  // float4 per row (1024 floats)
static constexpr int TOK_PER_BLK = 4;

__global__ void __launch_bounds__(128, 10) embed_gather_kernel(
    const int* __restrict__ ids,
    const float4* __restrict__ w,
    float4* __restrict__ out,
    int n_tokens)
{
    const int c0   = threadIdx.x;          // column 0..127
    const int c1   = threadIdx.x + 128;    // column 128..255
    const int tok0 = blockIdx.x * TOK_PER_BLK;

    if (tok0 + TOK_PER_BLK <= n_tokens) {
        const int r0 = __ldg(ids + tok0 + 0);
        const int r1 = __ldg(ids + tok0 + 1);
        const int r2 = __ldg(ids + tok0 + 2);
        const int r3 = __ldg(ids + tok0 + 3);

        // 8 independent gathers, front-batched
        float4 a0 = __ldg(w + (size_t)r0 * ROW_F4 + c0);
        float4 b0 = __ldg(w + (size_t)r0 * ROW_F4 + c1);
        float4 a1 = __ldg(w + (size_t)r1 * ROW_F4 + c0);
        float4 b1 = __ldg(w + (size_t)r1 * ROW_F4 + c1);
        float4 a2 = __ldg(w + (size_t)r2 * ROW_F4 + c0);
        float4 b2 = __ldg(w + (size_t)r2 * ROW_F4 + c1);
        float4 a3 = __ldg(w + (size_t)r3 * ROW_F4 + c0);
        float4 b3 = __ldg(w + (size_t)r3 * ROW_F4 + c1);

        __stcs(out + (size_t)(tok0 + 0) * ROW_F4 + c0, a0);
        __stcs(out + (size_t)(tok0 + 0) * ROW_F4 + c1, b0);
        __stcs(out + (size_t)(tok0 + 1) * ROW_F4 + c0, a1);
        __stcs(out + (size_t)(tok0 + 1) * ROW_F4 + c1, b1);
        __stcs(out + (size_t)(tok0 + 2) * ROW_F4 + c0, a2);
        __stcs(out + (size_t)(tok0 + 2) * ROW_F4 + c1, b2);
        __stcs(out + (size_t)(tok0 + 3) * ROW_F4 + c0, a3);
        __stcs(out + (size_t)(tok0 + 3) * ROW_F4 + c1, b3);
    } else {
        for (int t = tok0; t < n_tokens; ++t) {
            int r = __ldg(ids + t);
            __stcs(out + (size_t)t * ROW_F4 + c0, __ldg(w + (size_t)r * ROW_F4 + c0));
            __stcs(out + (size_t)t * ROW_F4 + c1, __ldg(w + (size_t)r * ROW_F4 + c1));
        }
    }
}

extern "C" void kernel_launch(void* const* d_in, const int* in_sizes, int n_in,
                              void* d_out, int out_size)
{
    const int*    ids = (const int*)d_in[0];
    const float4* w   = (const float4*)d_in[1];
    float4*       out = (float4*)d_out;

    int n_tokens = in_sizes[0];                                  // 16384
    int blocks   = (n_tokens + TOK_PER_BLK - 1) / TOK_PER_BLK;   // 4096
    embed_gather_kernel<<<blocks, 128>>>(ids, w, out, n_tokens);
}